// round 5
// baseline (speedup 1.0000x reference)
#include <cuda_runtime.h>
#include <cstdint>

#define COLS   24576
#define TPB    512
#define NWARP  (TPB / 32)          // 16
#define VPT    (COLS / (TPB * 4))  // 12 float4 per thread
#define SEGCAP 64
#define CANDCAP (NWARP * SEGCAP)   // 1024

__device__ __forceinline__ unsigned sortable_u(unsigned b) {
    // monotone map: float ordering -> unsigned ordering
    return b ^ ((unsigned)((int)b >> 31) | 0x80000000u);
}

__global__ __launch_bounds__(TPB) void topk_mask_kernel(
    const float* __restrict__ x, const int* __restrict__ kptr, float* __restrict__ out)
{
    __shared__ unsigned long long segKey[CANDCAP];
    __shared__ unsigned long long candKey[CANDCAP];
    __shared__ int segCnt[NWARP];
    __shared__ int segOff[NWARP];
    __shared__ int red[NWARP];
    __shared__ int sh_m;
    __shared__ int sh_fail;
    __shared__ int sh_tot;
    __shared__ unsigned sh_ucut;
    __shared__ int sh_icut;

    const int tid  = threadIdx.x;
    const int lane = tid & 31;
    const int warp = tid >> 5;
    const size_t rbase = (size_t)blockIdx.x * COLS;
    const float4* rx = reinterpret_cast<const float4*>(x + rbase);
    float4*       ro = reinterpret_cast<float4*>(out + rbase);

    int k = kptr ? kptr[0] : 64;   // int32 read also yields 64 from LE int64
    k = max(1, min(k, COLS));

    if (tid == 0) sh_fail = 0;
    __syncthreads();

    // ---------------- Pass 1: stream row, collect candidates >= THR ----------
    const float THR = 2.25f;   // P(N(0,1) > 2.25)*24576 ~ 300 candidates/row
    int cnt = 0;               // warp-uniform running count
    #pragma unroll
    for (int i = 0; i < VPT; i++) {
        const int v4 = tid + i * TPB;
        const float4 f = rx[v4];
        const int base = v4 * 4;
        float vals[4] = {f.x, f.y, f.z, f.w};
        #pragma unroll
        for (int j = 0; j < 4; j++) {
            const bool m = vals[j] >= THR;
            const unsigned bal = __ballot_sync(0xffffffffu, m);
            if (m) {
                const int pos = cnt + __popc(bal & ((1u << lane) - 1u));
                if (pos < SEGCAP) {
                    const unsigned u = __float_as_uint(vals[j]) | 0x80000000u; // positive
                    // key: value desc, then index asc (stable top_k tie-break)
                    segKey[warp * SEGCAP + pos] =
                        ((unsigned long long)u << 15) | (unsigned)(0x7FFF - (base + j));
                }
            }
            cnt += __popc(bal);
        }
    }
    if (lane == 0) {
        segCnt[warp] = min(cnt, SEGCAP);
        if (cnt > SEGCAP) sh_fail = 1;
    }
    __syncthreads();

    // prefix-sum of per-warp counts (warp 0)
    if (warp == 0) {
        int c = (lane < NWARP) ? segCnt[lane] : 0;
        int s = c;
        #pragma unroll
        for (int d = 1; d < 32; d <<= 1) {
            int t = __shfl_up_sync(0xffffffffu, s, d);
            if (lane >= d) s += t;
        }
        if (lane < NWARP) segOff[lane] = s - c;
        if (lane == NWARP - 1) sh_m = s;
    }
    __syncthreads();

    const int m = sh_m;
    const bool fail = (sh_fail != 0) || (m < k);   // block-uniform

    if (!fail) {
        // -------- compact candidates, then rank-by-counting --------
        {
            const int c = segCnt[warp], off = segOff[warp];
            for (int j = lane; j < c; j += 32)
                candKey[off + j] = segKey[warp * SEGCAP + j];
        }
        __syncthreads();
        for (int j = tid; j < m; j += TPB) {
            const unsigned long long kj = candKey[j];
            int r = 0;
            for (int i = 0; i < m; i++) r += (candKey[i] > kj) ? 1 : 0;
            if (r == k - 1) {   // exactly one (keys unique via idx)
                sh_ucut = (unsigned)(kj >> 15);
                sh_icut = 0x7FFF - (int)(kj & 0x7FFFull);
            }
        }
        __syncthreads();
    } else {
        // -------- exact fallback: bisection on sortable value, then index ----
        auto blockSum = [&](int c) -> int {
            #pragma unroll
            for (int d = 16; d; d >>= 1) c += __shfl_down_sync(0xffffffffu, c, d);
            __syncthreads();
            if (lane == 0) red[warp] = c;
            __syncthreads();
            if (tid == 0) {
                int t = 0;
                for (int w = 0; w < NWARP; w++) t += red[w];
                sh_tot = t;
            }
            __syncthreads();
            return sh_tot;
        };
        auto countGE = [&](unsigned v) -> int {
            int c = 0;
            for (int i = 0; i < VPT; i++) {
                const float4 f = rx[tid + i * TPB];
                c += (sortable_u(__float_as_uint(f.x)) >= v);
                c += (sortable_u(__float_as_uint(f.y)) >= v);
                c += (sortable_u(__float_as_uint(f.z)) >= v);
                c += (sortable_u(__float_as_uint(f.w)) >= v);
            }
            return blockSum(c);
        };
        auto countEQLE = [&](unsigned v, int idxle) -> int {
            int c = 0;
            for (int i = 0; i < VPT; i++) {
                const int v4 = tid + i * TPB;
                const float4 f = rx[v4];
                const int base = v4 * 4;
                c += (sortable_u(__float_as_uint(f.x)) == v && base + 0 <= idxle);
                c += (sortable_u(__float_as_uint(f.y)) == v && base + 1 <= idxle);
                c += (sortable_u(__float_as_uint(f.z)) == v && base + 2 <= idxle);
                c += (sortable_u(__float_as_uint(f.w)) == v && base + 3 <= idxle);
            }
            return blockSum(c);
        };

        unsigned lo = 0u, hi = 0xFFFFFFFFu;      // max v with countGE(v) >= k
        while (lo < hi) {
            const unsigned mid = lo + ((hi - lo) >> 1) + 1u;
            if (countGE(mid) >= k) lo = mid; else hi = mid - 1u;
        }
        const unsigned ucut = lo;
        const int cgt  = (ucut == 0xFFFFFFFFu) ? 0 : countGE(ucut + 1u);
        const int need = k - cgt;
        int l2 = 0, h2 = COLS - 1;               // smallest idx with countEQLE >= need
        while (l2 < h2) {
            const int mid = (l2 + h2) >> 1;
            if (countEQLE(ucut, mid) >= need) h2 = mid; else l2 = mid + 1;
        }
        if (tid == 0) { sh_ucut = ucut; sh_icut = l2; }
        __syncthreads();
    }

    const unsigned ucut = sh_ucut;
    const int      icut = sh_icut;

    // ---------------- Pass 2: re-read (L2 hit) and write masked row ----------
    #pragma unroll
    for (int i = 0; i < VPT; i++) {
        const int v4 = tid + i * TPB;
        const float4 f = __ldcs(rx + v4);
        const int base = v4 * 4;
        float4 o;
        {
            const unsigned u = sortable_u(__float_as_uint(f.x));
            o.x = (u > ucut || (u == ucut && base + 0 <= icut)) ? f.x : 0.0f;
        }
        {
            const unsigned u = sortable_u(__float_as_uint(f.y));
            o.y = (u > ucut || (u == ucut && base + 1 <= icut)) ? f.y : 0.0f;
        }
        {
            const unsigned u = sortable_u(__float_as_uint(f.z));
            o.z = (u > ucut || (u == ucut && base + 2 <= icut)) ? f.z : 0.0f;
        }
        {
            const unsigned u = sortable_u(__float_as_uint(f.w));
            o.w = (u > ucut || (u == ucut && base + 3 <= icut)) ? f.w : 0.0f;
        }
        __stcs(ro + v4, o);
    }
}

extern "C" void kernel_launch(void* const* d_in, const int* in_sizes, int n_in,
                              void* d_out, int out_size)
{
    const float* x  = (const float*)d_in[0];
    const int*   kp = (n_in >= 2) ? (const int*)d_in[1] : nullptr;
    const int rows = in_sizes[0] / COLS;
    if (rows <= 0) return;
    topk_mask_kernel<<<rows, TPB>>>(x, kp, (float*)d_out);
}